// round 11
// baseline (speedup 1.0000x reference)
#include <cuda_runtime.h>
#include <cuda_fp16.h>
#include <math_constants.h>
#include <cstdint>

#define BATCH 2
#define SEQ   2048
#define DM    1024
#define NH    16
#define DK    64
#define M_TOT (BATCH*SEQ)   // 4096

// -------- scratch (device globals: allocation-free) --------
__device__ __half g_Qh [(size_t)BATCH*NH*SEQ*DK];   // pre-scaled by 0.125*log2(e)
__device__ __half g_Kh [(size_t)BATCH*NH*SEQ*DK];
__device__ __half g_Vh [(size_t)BATCH*NH*SEQ*DK];
__device__ __half g_ctxh[(size_t)M_TOT*DM];
__device__ __half g_xh   [(size_t)M_TOT*DM];
__device__ __half g_wqkvh[(size_t)3*DM*DM];
__device__ __half g_wouth[(size_t)DM*DM];

// -------- helpers --------
__device__ __forceinline__ void cp_async16(uint32_t smem, const void* gmem) {
    asm volatile("cp.async.cg.shared.global [%0], [%1], 16;\n" :: "r"(smem), "l"(gmem));
}
__device__ __forceinline__ void cp_commit() { asm volatile("cp.async.commit_group;\n"); }
template<int N> __device__ __forceinline__ void cp_wait() {
    asm volatile("cp.async.wait_group %0;\n" :: "n"(N));
}
__device__ __forceinline__ unsigned h2_as_u32(__half2 h) {
    return *reinterpret_cast<unsigned*>(&h);
}
__device__ __forceinline__ uint32_t smem_u32(const void* p) {
    return (uint32_t)__cvta_generic_to_shared(p);
}
__device__ __forceinline__ void ldsm_x4(unsigned& r0, unsigned& r1, unsigned& r2, unsigned& r3,
                                        uint32_t addr) {
    asm volatile("ldmatrix.sync.aligned.m8n8.x4.shared.b16 {%0,%1,%2,%3}, [%4];"
                 : "=r"(r0), "=r"(r1), "=r"(r2), "=r"(r3) : "r"(addr));
}
__device__ __forceinline__ void mma_f16(float* d, const unsigned* a, unsigned b0, unsigned b1) {
    asm volatile(
        "mma.sync.aligned.m16n8k16.row.col.f32.f16.f16.f32 "
        "{%0,%1,%2,%3},{%4,%5,%6,%7},{%8,%9},{%0,%1,%2,%3};\n"
        : "+f"(d[0]),"+f"(d[1]),"+f"(d[2]),"+f"(d[3])
        : "r"(a[0]),"r"(a[1]),"r"(a[2]),"r"(a[3]),"r"(b0),"r"(b1));
}

// ============================================================
// fused fp32 -> fp16 conversion prepass (one launch)
// ============================================================
__global__ void prep_kernel(const float4* __restrict__ x,
                            const float4* __restrict__ wq,
                            const float4* __restrict__ wo,
                            uint2* __restrict__ xh,
                            uint2* __restrict__ wqh,
                            uint2* __restrict__ woh)
{
    const int stride = gridDim.x * blockDim.x;
    const int t0 = blockIdx.x*blockDim.x + threadIdx.x;
    #pragma unroll 1
    for (int i = t0; i < (M_TOT*DM)/4; i += stride) {
        float4 v = x[i];
        xh[i] = make_uint2(h2_as_u32(__floats2half2_rn(v.x, v.y)),
                           h2_as_u32(__floats2half2_rn(v.z, v.w)));
    }
    #pragma unroll 1
    for (int i = t0; i < (3*DM*DM)/4; i += stride) {
        float4 v = wq[i];
        wqh[i] = make_uint2(h2_as_u32(__floats2half2_rn(v.x, v.y)),
                            h2_as_u32(__floats2half2_rn(v.z, v.w)));
    }
    #pragma unroll 1
    for (int i = t0; i < (DM*DM)/4; i += stride) {
        float4 v = wo[i];
        woh[i] = make_uint2(h2_as_u32(__floats2half2_rn(v.x, v.y)),
                            h2_as_u32(__floats2half2_rn(v.z, v.w)));
    }
}

// ============================================================
// fp16 mma GEMM:  C[M,N] = A[M,1024] * W[N,1024]^T + bias[N]
// CTA 128x128, BK=64, 8 warps, warp tile 32x64. 3-stage cp.async
// pipeline, one __syncthreads per iteration. Prefetch is issued
// as 4 SMALL bursts (one after each k-step) with a single commit,
// so the LSU never clumps against the LDSM fragment restart.
// MODE 0 -> Q(x0.125*log2e)/K/V fp16 scratch; MODE 1 -> fp32 out.
// ============================================================
#define GSTG 16384
#define GEMM_SMEM (6*GSTG)   // 3 x A(16KB) + 3 x B(16KB)

template<int MODE>
__global__ __launch_bounds__(256, 2)
void gemm_f16_kernel(const float* __restrict__ bias, float* __restrict__ Cout)
{
    extern __shared__ char smraw[];
    const uint32_t sa = smem_u32(smraw);            // A stages [0,3)
    const uint32_t sb = sa + 3*GSTG;                // B stages [0,3)

    const int tid  = threadIdx.x;
    const int warp = tid >> 5;
    const int lane = tid & 31;
    const int wm   = warp >> 1;      // 0..3
    const int wn   = warp & 1;       // 0..1
    const int bm   = blockIdx.y;
    const int bn   = blockIdx.x;

    const __half* Ab = (MODE == 0 ? g_xh : g_ctxh) + (size_t)(bm*128)*1024;
    const __half* Wb = (MODE == 0 ? g_wqkvh : g_wouth) + (size_t)(bn*128)*1024;

    float acc[2][8][4];
    #pragma unroll
    for (int x=0;x<2;x++)
        #pragma unroll
        for (int j=0;j<8;j++)
            #pragma unroll
            for (int e=0;e<4;e++) acc[x][j][e] = 0.0f;

    // issue 2 of the 8 cp.async sub-bursts for stage ci
    auto preload_part = [&](int ci, int p) {
        const int st = ci % 3;
        const uint32_t ab = sa + st*GSTG;
        const uint32_t bb = sb + st*GSTG;
        #pragma unroll
        for (int it = 2*p; it < 2*p + 2; it++) {
            int s = tid + it*256;                   // 0..2047
            if (s < 1024) {                          // A: 128 rows x 8 segs(16B)
                int row = s >> 3, seg = s & 7;
                cp_async16(ab + row*128 + ((seg*16) ^ ((row&7)*16)),
                           Ab + (size_t)row*1024 + ci*64 + seg*8);
            } else {                                 // B
                int q = s - 1024;
                int row = q >> 3, seg = q & 7;
                cp_async16(bb + row*128 + ((seg*16) ^ ((row&7)*16)),
                           Wb + (size_t)row*1024 + ci*64 + seg*8);
            }
        }
    };
    auto preload_all = [&](int ci) {
        #pragma unroll
        for (int p = 0; p < 4; p++) preload_part(ci, p);
    };

    preload_all(0); cp_commit();
    preload_all(1); cp_commit();

    for (int i = 0; i < 16; i++) {
        if (i < 15) cp_wait<1>(); else cp_wait<0>();
        __syncthreads();

        const uint32_t ab = sa + (i%3)*GSTG;
        const uint32_t bb = sb + (i%3)*GSTG;
        const bool pf = (i + 2 < 16);

        auto ks_step = [&](int ks) {
            unsigned af[2][4];
            #pragma unroll
            for (int x = 0; x < 2; x++) {
                int lrow = wm*32 + x*16 + (lane & 15);
                int kb   = ks*32 + (lane >> 4)*16;
                ldsm_x4(af[x][0], af[x][1], af[x][2], af[x][3],
                        ab + lrow*128 + (kb ^ ((lrow&7)*16)));
            }
            #pragma unroll
            for (int jj = 0; jj < 4; jj++) {
                int nrow = wn*64 + jj*16 + (lane & 7) + (lane >> 4)*8;
                int kb   = ks*32 + ((lane >> 3) & 1)*16;
                unsigned b0,b1,b2,b3;
                ldsm_x4(b0, b1, b2, b3, bb + nrow*128 + (kb ^ ((nrow&7)*16)));
                #pragma unroll
                for (int x = 0; x < 2; x++) {
                    mma_f16(acc[x][2*jj  ], af[x], b0, b1);
                    mma_f16(acc[x][2*jj+1], af[x], b2, b3);
                }
            }
        };

        // k-steps with prefetch spread thinly between them
        ks_step(0);
        if (pf) preload_part(i+2, 0);
        ks_step(1);
        if (pf) preload_part(i+2, 1);
        ks_step(2);
        if (pf) preload_part(i+2, 2);
        ks_step(3);
        if (pf) { preload_part(i+2, 3); cp_commit(); }
    }
    __syncthreads();   // all fragment reads done before stage overlays smem

    // ---- epilogue via per-warp smem staging ----
    float* stage = (float*)smraw + warp*16*20;
    const int r = lane >> 2, c = lane & 3;
    #pragma unroll
    for (int x = 0; x < 2; x++) {
        #pragma unroll
        for (int jj = 0; jj < 4; jj++) {
            stage[ r    *20 + 2*c    ] = acc[x][2*jj][0];
            stage[ r    *20 + 2*c + 1] = acc[x][2*jj][1];
            stage[(r+8) *20 + 2*c    ] = acc[x][2*jj][2];
            stage[(r+8) *20 + 2*c + 1] = acc[x][2*jj][3];
            stage[ r    *20 + 8 + 2*c    ] = acc[x][2*jj+1][0];
            stage[ r    *20 + 8 + 2*c + 1] = acc[x][2*jj+1][1];
            stage[(r+8) *20 + 8 + 2*c    ] = acc[x][2*jj+1][2];
            stage[(r+8) *20 + 8 + 2*c + 1] = acc[x][2*jj+1][3];
            __syncwarp();
            #pragma unroll
            for (int e = 0; e < 8; e++) {
                int idx = e*32 + lane;
                int rr = idx >> 4, cc = idx & 15;
                int gm = bm*128 + wm*32 + x*16 + rr;
                int gn = bn*128 + wn*64 + jj*16 + cc;
                float v = stage[rr*20 + cc] + __ldg(&bias[gn]);
                if (MODE == 0) {
                    int b = gm >> 11, t = gm & 2047;
                    int part = gn >> 10, rem = gn & 1023;
                    int h = rem >> 6, d = rem & 63;
                    size_t off = (((size_t)(b*NH + h))*SEQ + t)*DK + d;
                    if (part == 0)      g_Qh[off] = __float2half_rn(v * 0.1803368801f); // 0.125*log2(e)
                    else if (part == 1) g_Kh[off] = __float2half_rn(v);
                    else                g_Vh[off] = __float2half_rn(v);
                } else {
                    Cout[(size_t)gm*DM + gn] = v;
                }
            }
            __syncwarp();
        }
    }
}

// ============================================================
// FlashAttention-2, all-fp16, 6-stage KV pipeline with ONE
// __syncthreads per 2 key-tiles. Each tile prefetches tile kt+4
// (one 4-burst preload per tile, landed in the softmax window).
// S = Q K^T with K B-fragments via ldmatrix.x4; softmax base-2;
// P fp16 regs; O += P V via ldmatrix.trans.
// ============================================================
#define KV_LD 72                       // halves per K/V row
#define KVBUF (64*KV_LD)               // halves per stage
#define ASTAGES 6
#define ATTN_SMEM (2*ASTAGES*KVBUF*2)  // 6 x K + 6 x V = 110592 B

__global__ __launch_bounds__(256, 2)
void attn_kernel()
{
    extern __shared__ char smraw[];
    __half* Ksm = (__half*)smraw;                 // 6 x 64 x 72
    __half* Vsm = Ksm + ASTAGES*KVBUF;            // 6 x 64 x 72

    const int tid  = threadIdx.x;
    const int warp = tid >> 5;
    const int lane = tid & 31;
    const int r    = lane >> 2;      // 0..7
    const int c    = lane & 3;       // 0..3
    const int q0   = blockIdx.x * 128;
    const int h    = blockIdx.y;
    const int b    = blockIdx.z;
    const size_t headbase = ((size_t)(b*NH + h))*SEQ*DK;

    // ---- Q fragments (fp16, pre-scaled incl. log2e) from gmem ----
    unsigned qf[4][4];
    {
        const __half* q_r0 = g_Qh + headbase + (size_t)(q0 + warp*16 + r)*DK;
        const __half* q_r1 = q_r0 + 8*DK;
        #pragma unroll
        for (int s = 0; s < 4; s++) {
            qf[s][0] = *(const unsigned*)(q_r0 + 16*s + 2*c);
            qf[s][1] = *(const unsigned*)(q_r1 + 16*s + 2*c);
            qf[s][2] = *(const unsigned*)(q_r0 + 16*s + 2*c + 8);
            qf[s][3] = *(const unsigned*)(q_r1 + 16*s + 2*c + 8);
        }
    }

    float Oacc[8][4];
    #pragma unroll
    for (int j=0;j<8;j++)
        #pragma unroll
        for (int e=0;e<4;e++) Oacc[j][e] = 0.0f;
    float mrow[2] = {-CUDART_INF_F, -CUDART_INF_F};
    float lrow[2] = {0.0f, 0.0f};

    const uint32_t kbase0 = smem_u32(Ksm);
    const uint32_t vbase0 = smem_u32(Vsm);

    auto preload = [&](int kt) {
        const int st = kt % ASTAGES;
        const size_t kb = headbase + (size_t)kt*64*DK;
        const uint32_t kd = kbase0 + (uint32_t)(st*KVBUF*2);
        const uint32_t vd = vbase0 + (uint32_t)(st*KVBUF*2);
        #pragma unroll
        for (int it = 0; it < 2; it++) {             // K: 512 x 16B
            int idx = tid + it*256;
            int row = idx >> 3, seg = idx & 7;
            cp_async16(kd + row*KV_LD*2 + seg*16, g_Kh + kb + (size_t)row*DK + seg*8);
        }
        #pragma unroll
        for (int it = 0; it < 2; it++) {             // V: 512 x 16B
            int idx = tid + it*256;
            int row = idx >> 3, seg = idx & 7;
            cp_async16(vd + row*KV_LD*2 + seg*16, g_Vh + kb + (size_t)row*DK + seg*8);
        }
    };

    preload(0); cp_commit();
    preload(1); cp_commit();
    preload(2); cp_commit();
    preload(3); cp_commit();

    const int n_off = ((lane >> 4) << 3) + (lane & 7);   // (group>>1)*8 + row
    const int c_off = ((lane >> 3) & 1) << 3;            // (group&1)*8
    const int t  = lane >> 3;
    const int rr = lane & 7;

    // one key-tile: S-mma, prefetch kt+4, softmax, PV
    auto do_tile = [&](int kt) {
        const int st = kt % ASTAGES;
        const uint32_t kb32 = kbase0 + (uint32_t)(st*KVBUF*2);
        const uint32_t vb   = vbase0 + (uint32_t)(st*KVBUF*2);

        // ---- S = Q K^T ----
        float Sacc[8][4];
        #pragma unroll
        for (int j=0;j<8;j++)
            #pragma unroll
            for (int e=0;e<4;e++) Sacc[j][e] = 0.0f;
        #pragma unroll
        for (int s = 0; s < 4; s++) {
            #pragma unroll
            for (int jp = 0; jp < 4; jp++) {
                uint32_t addr = kb32 + (uint32_t)((((16*jp + n_off)*KV_LD) + 16*s + c_off)*2);
                unsigned b0,b1,b2,b3;
                ldsm_x4(b0, b1, b2, b3, addr);
                mma_f16(Sacc[2*jp  ], qf[s], b0, b1);
                mma_f16(Sacc[2*jp+1], qf[s], b2, b3);
            }
        }

        // prefetch tile kt+4 (stage (kt-2)%6 — last read before this
        // pair's barrier; disjoint from the pair's tiles)
        if (kt + 4 < SEQ/64) { preload(kt+4); cp_commit(); }

        // ---- online softmax (base-2) ----
        float mx0 = Sacc[0][0], mx1 = Sacc[0][2];
        #pragma unroll
        for (int j=0;j<8;j++) {
            mx0 = fmaxf(mx0, fmaxf(Sacc[j][0], Sacc[j][1]));
            mx1 = fmaxf(mx1, fmaxf(Sacc[j][2], Sacc[j][3]));
        }
        mx0 = fmaxf(mx0, __shfl_xor_sync(0xffffffffu, mx0, 1));
        mx0 = fmaxf(mx0, __shfl_xor_sync(0xffffffffu, mx0, 2));
        mx1 = fmaxf(mx1, __shfl_xor_sync(0xffffffffu, mx1, 1));
        mx1 = fmaxf(mx1, __shfl_xor_sync(0xffffffffu, mx1, 2));
        float mn0 = fmaxf(mrow[0], mx0), mn1 = fmaxf(mrow[1], mx1);
        float al0 = exp2f(mrow[0] - mn0), al1 = exp2f(mrow[1] - mn1);
        mrow[0] = mn0; mrow[1] = mn1;

        unsigned ph[16];
        float sum0 = 0.0f, sum1 = 0.0f;
        #pragma unroll
        for (int j = 0; j < 8; j++) {
            float p0 = exp2f(Sacc[j][0] - mn0);
            float p1 = exp2f(Sacc[j][1] - mn0);
            float p2 = exp2f(Sacc[j][2] - mn1);
            float p3 = exp2f(Sacc[j][3] - mn1);
            sum0 += p0 + p1; sum1 += p2 + p3;
            ph[2*j  ] = h2_as_u32(__floats2half2_rn(p0, p1));
            ph[2*j+1] = h2_as_u32(__floats2half2_rn(p2, p3));
        }
        sum0 += __shfl_xor_sync(0xffffffffu, sum0, 1);
        sum0 += __shfl_xor_sync(0xffffffffu, sum0, 2);
        sum1 += __shfl_xor_sync(0xffffffffu, sum1, 1);
        sum1 += __shfl_xor_sync(0xffffffffu, sum1, 2);
        lrow[0] = lrow[0]*al0 + sum0;
        lrow[1] = lrow[1]*al1 + sum1;
        #pragma unroll
        for (int j=0;j<8;j++) {
            Oacc[j][0] *= al0; Oacc[j][1] *= al0;
            Oacc[j][2] *= al1; Oacc[j][3] *= al1;
        }

        // ---- O += P V ----
        #pragma unroll
        for (int s = 0; s < 4; s++) {
            const unsigned* af = &ph[4*s];
            #pragma unroll
            for (int g = 0; g < 4; g++) {
                uint32_t addr = vb + (uint32_t)(((16*s + (t&1)*8 + rr)*KV_LD + (t>>1)*8 + g*16)*2);
                unsigned r0,r1,r2,r3;
                asm volatile(
                    "ldmatrix.sync.aligned.m8n8.x4.trans.shared.b16 {%0,%1,%2,%3}, [%4];\n"
                    : "=r"(r0),"=r"(r1),"=r"(r2),"=r"(r3) : "r"(addr));
                mma_f16(Oacc[2*g  ], af, r0, r1);
                mma_f16(Oacc[2*g+1], af, r2, r3);
            }
        }
    };

    #pragma unroll 1
    for (int kt = 0; kt < SEQ/64; kt += 2) {
        if (kt < SEQ/64 - 2) cp_wait<2>(); else cp_wait<0>();
        __syncthreads();
        do_tile(kt);
        do_tile(kt + 1);
    }

    // ---- normalize + write ctx fp16 [B,T,DM] ----
    {
        float inv0 = 1.0f / lrow[0];
        float inv1 = 1.0f / lrow[1];
        __half* row0 = g_ctxh + ((size_t)(b*SEQ + q0 + warp*16 + r    ))*DM + h*DK;
        __half* row1 = g_ctxh + ((size_t)(b*SEQ + q0 + warp*16 + r + 8))*DM + h*DK;
        #pragma unroll
        for (int j = 0; j < 8; j++) {
            *(__half2*)(row0 + 8*j + 2*c) = __floats2half2_rn(Oacc[j][0]*inv0, Oacc[j][1]*inv0);
            *(__half2*)(row1 + 8*j + 2*c) = __floats2half2_rn(Oacc[j][2]*inv1, Oacc[j][3]*inv1);
        }
    }
}

// ============================================================
extern "C" void kernel_launch(void* const* d_in, const int* in_sizes, int n_in,
                              void* d_out, int out_size)
{
    (void)in_sizes; (void)n_in; (void)out_size;
    const float* x     = (const float*)d_in[0];
    const float* w_qkv = (const float*)d_in[1];
    const float* b_qkv = (const float*)d_in[2];
    const float* w_out = (const float*)d_in[3];
    const float* b_out = (const float*)d_in[4];
    float* out = (float*)d_out;

    cudaFuncSetAttribute(gemm_f16_kernel<0>, cudaFuncAttributeMaxDynamicSharedMemorySize, GEMM_SMEM);
    cudaFuncSetAttribute(gemm_f16_kernel<1>, cudaFuncAttributeMaxDynamicSharedMemorySize, GEMM_SMEM);
    cudaFuncSetAttribute(attn_kernel, cudaFuncAttributeMaxDynamicSharedMemorySize, ATTN_SMEM);

    void *xh, *wqkvh, *wouth;
    cudaGetSymbolAddress(&xh,    g_xh);
    cudaGetSymbolAddress(&wqkvh, g_wqkvh);
    cudaGetSymbolAddress(&wouth, g_wouth);

    // 0) fused fp32 -> fp16 prepass (one launch)
    prep_kernel<<<1024, 256>>>((const float4*)x, (const float4*)w_qkv, (const float4*)w_out,
                               (uint2*)xh, (uint2*)wqkvh, (uint2*)wouth);

    // 1) QKV projection -> Q/K/V fp16 scratch
    gemm_f16_kernel<0><<<dim3(3*DM/128, M_TOT/128), 256, GEMM_SMEM>>>(b_qkv, nullptr);
    // 2) attention -> ctx fp16 scratch
    attn_kernel<<<dim3(SEQ/128, NH, BATCH), 256, ATTN_SMEM>>>();
    // 3) output projection -> d_out fp32
    gemm_f16_kernel<1><<<dim3(DM/128, M_TOT/128), 256, GEMM_SMEM>>>(b_out, out);
}

// round 13
// speedup vs baseline: 1.0806x; 1.0806x over previous
#include <cuda_runtime.h>
#include <cuda_fp16.h>
#include <math_constants.h>
#include <cstdint>

#define BATCH 2
#define SEQ   2048
#define DM    1024
#define NH    16
#define DK    64
#define M_TOT (BATCH*SEQ)   // 4096

// -------- scratch (device globals: allocation-free) --------
__device__ __half g_Qh [(size_t)BATCH*NH*SEQ*DK];   // pre-scaled by 0.125*log2(e)
__device__ __half g_Kh [(size_t)BATCH*NH*SEQ*DK];
__device__ __half g_Vh [(size_t)BATCH*NH*SEQ*DK];
__device__ __half g_ctxh[(size_t)M_TOT*DM];
__device__ __half g_xh   [(size_t)M_TOT*DM];
__device__ __half g_wqkvh[(size_t)3*DM*DM];
__device__ __half g_wouth[(size_t)DM*DM];

// -------- helpers --------
__device__ __forceinline__ void cp_async16(uint32_t smem, const void* gmem) {
    asm volatile("cp.async.cg.shared.global [%0], [%1], 16;\n" :: "r"(smem), "l"(gmem));
}
__device__ __forceinline__ void cp_commit() { asm volatile("cp.async.commit_group;\n"); }
template<int N> __device__ __forceinline__ void cp_wait() {
    asm volatile("cp.async.wait_group %0;\n" :: "n"(N));
}
__device__ __forceinline__ unsigned h2_as_u32(__half2 h) {
    return *reinterpret_cast<unsigned*>(&h);
}
__device__ __forceinline__ uint32_t smem_u32(const void* p) {
    return (uint32_t)__cvta_generic_to_shared(p);
}
__device__ __forceinline__ void ldsm_x4(unsigned& r0, unsigned& r1, unsigned& r2, unsigned& r3,
                                        uint32_t addr) {
    asm volatile("ldmatrix.sync.aligned.m8n8.x4.shared.b16 {%0,%1,%2,%3}, [%4];"
                 : "=r"(r0), "=r"(r1), "=r"(r2), "=r"(r3) : "r"(addr));
}
__device__ __forceinline__ void mma_f16(float* d, const unsigned* a, unsigned b0, unsigned b1) {
    asm volatile(
        "mma.sync.aligned.m16n8k16.row.col.f32.f16.f16.f32 "
        "{%0,%1,%2,%3},{%4,%5,%6,%7},{%8,%9},{%0,%1,%2,%3};\n"
        : "+f"(d[0]),"+f"(d[1]),"+f"(d[2]),"+f"(d[3])
        : "r"(a[0]),"r"(a[1]),"r"(a[2]),"r"(a[3]),"r"(b0),"r"(b1));
}
__device__ __forceinline__ unsigned ex2_h2(unsigned x) {
    unsigned d;
    asm("ex2.approx.f16x2 %0, %1;" : "=r"(d) : "r"(x));
    return d;
}

// ============================================================
// fused fp32 -> fp16 conversion prepass (one launch)
// ============================================================
__global__ void prep_kernel(const float4* __restrict__ x,
                            const float4* __restrict__ wq,
                            const float4* __restrict__ wo,
                            uint2* __restrict__ xh,
                            uint2* __restrict__ wqh,
                            uint2* __restrict__ woh)
{
    const int stride = gridDim.x * blockDim.x;
    const int t0 = blockIdx.x*blockDim.x + threadIdx.x;
    #pragma unroll 1
    for (int i = t0; i < (M_TOT*DM)/4; i += stride) {
        float4 v = x[i];
        xh[i] = make_uint2(h2_as_u32(__floats2half2_rn(v.x, v.y)),
                           h2_as_u32(__floats2half2_rn(v.z, v.w)));
    }
    #pragma unroll 1
    for (int i = t0; i < (3*DM*DM)/4; i += stride) {
        float4 v = wq[i];
        wqh[i] = make_uint2(h2_as_u32(__floats2half2_rn(v.x, v.y)),
                            h2_as_u32(__floats2half2_rn(v.z, v.w)));
    }
    #pragma unroll 1
    for (int i = t0; i < (DM*DM)/4; i += stride) {
        float4 v = wo[i];
        woh[i] = make_uint2(h2_as_u32(__floats2half2_rn(v.x, v.y)),
                            h2_as_u32(__floats2half2_rn(v.z, v.w)));
    }
}

// ============================================================
// fp16 mma GEMM (round-10 best schedule):  C = A * W^T + bias
// CTA 128x128, BK=64, 8 warps, warp tile 32x64. 3-stage cp.async
// pipeline, one __syncthreads per iteration; single prefetch
// burst issued after the first k-step.
// MODE 0 -> Q(x0.125*log2e)/K/V fp16 scratch; MODE 1 -> fp32 out.
// ============================================================
#define GSTG 16384
#define GEMM_SMEM (6*GSTG)   // 3 x A(16KB) + 3 x B(16KB)

template<int MODE>
__global__ __launch_bounds__(256, 2)
void gemm_f16_kernel(const float* __restrict__ bias, float* __restrict__ Cout)
{
    extern __shared__ char smraw[];
    const uint32_t sa = smem_u32(smraw);            // A stages [0,3)
    const uint32_t sb = sa + 3*GSTG;                // B stages [0,3)

    const int tid  = threadIdx.x;
    const int warp = tid >> 5;
    const int lane = tid & 31;
    const int wm   = warp >> 1;      // 0..3
    const int wn   = warp & 1;       // 0..1
    const int bm   = blockIdx.y;
    const int bn   = blockIdx.x;

    const __half* Ab = (MODE == 0 ? g_xh : g_ctxh) + (size_t)(bm*128)*1024;
    const __half* Wb = (MODE == 0 ? g_wqkvh : g_wouth) + (size_t)(bn*128)*1024;

    float acc[2][8][4];
    #pragma unroll
    for (int x=0;x<2;x++)
        #pragma unroll
        for (int j=0;j<8;j++)
            #pragma unroll
            for (int e=0;e<4;e++) acc[x][j][e] = 0.0f;

    auto preload = [&](int ci) {
        const int st = ci % 3;
        const uint32_t ab = sa + st*GSTG;
        const uint32_t bb = sb + st*GSTG;
        #pragma unroll
        for (int it = 0; it < 8; it++) {
            int s = tid + it*256;                   // 0..2047
            if (s < 1024) {                          // A: 128 rows x 8 segs(16B)
                int row = s >> 3, seg = s & 7;
                cp_async16(ab + row*128 + ((seg*16) ^ ((row&7)*16)),
                           Ab + (size_t)row*1024 + ci*64 + seg*8);
            } else {                                 // B
                int q = s - 1024;
                int row = q >> 3, seg = q & 7;
                cp_async16(bb + row*128 + ((seg*16) ^ ((row&7)*16)),
                           Wb + (size_t)row*1024 + ci*64 + seg*8);
            }
        }
    };

    preload(0); cp_commit();
    preload(1); cp_commit();

    for (int i = 0; i < 16; i++) {
        if (i < 15) cp_wait<1>(); else cp_wait<0>();
        __syncthreads();

        const uint32_t ab = sa + (i%3)*GSTG;
        const uint32_t bb = sb + (i%3)*GSTG;

        auto ks_step = [&](int ks) {
            unsigned af[2][4];
            #pragma unroll
            for (int x = 0; x < 2; x++) {
                int lrow = wm*32 + x*16 + (lane & 15);
                int kb   = ks*32 + (lane >> 4)*16;
                ldsm_x4(af[x][0], af[x][1], af[x][2], af[x][3],
                        ab + lrow*128 + (kb ^ ((lrow&7)*16)));
            }
            #pragma unroll
            for (int jj = 0; jj < 4; jj++) {
                int nrow = wn*64 + jj*16 + (lane & 7) + (lane >> 4)*8;
                int kb   = ks*32 + ((lane >> 3) & 1)*16;
                unsigned b0,b1,b2,b3;
                ldsm_x4(b0, b1, b2, b3, bb + nrow*128 + (kb ^ ((nrow&7)*16)));
                #pragma unroll
                for (int x = 0; x < 2; x++) {
                    mma_f16(acc[x][2*jj  ], af[x], b0, b1);
                    mma_f16(acc[x][2*jj+1], af[x], b2, b3);
                }
            }
        };

        // first k-step right after the barrier -> tensor pipe restarts at once
        ks_step(0);
        if (i + 2 < 16) { preload(i+2); cp_commit(); }
        #pragma unroll
        for (int ks = 1; ks < 4; ks++) ks_step(ks);
    }
    __syncthreads();   // all fragment reads done before stage overlays smem

    // ---- epilogue via per-warp smem staging ----
    float* stage = (float*)smraw + warp*16*20;
    const int r = lane >> 2, c = lane & 3;
    #pragma unroll
    for (int x = 0; x < 2; x++) {
        #pragma unroll
        for (int jj = 0; jj < 4; jj++) {
            stage[ r    *20 + 2*c    ] = acc[x][2*jj][0];
            stage[ r    *20 + 2*c + 1] = acc[x][2*jj][1];
            stage[(r+8) *20 + 2*c    ] = acc[x][2*jj][2];
            stage[(r+8) *20 + 2*c + 1] = acc[x][2*jj][3];
            stage[ r    *20 + 8 + 2*c    ] = acc[x][2*jj+1][0];
            stage[ r    *20 + 8 + 2*c + 1] = acc[x][2*jj+1][1];
            stage[(r+8) *20 + 8 + 2*c    ] = acc[x][2*jj+1][2];
            stage[(r+8) *20 + 8 + 2*c + 1] = acc[x][2*jj+1][3];
            __syncwarp();
            #pragma unroll
            for (int e = 0; e < 8; e++) {
                int idx = e*32 + lane;
                int rr = idx >> 4, cc = idx & 15;
                int gm = bm*128 + wm*32 + x*16 + rr;
                int gn = bn*128 + wn*64 + jj*16 + cc;
                float v = stage[rr*20 + cc] + __ldg(&bias[gn]);
                if (MODE == 0) {
                    int b = gm >> 11, t = gm & 2047;
                    int part = gn >> 10, rem = gn & 1023;
                    int h = rem >> 6, d = rem & 63;
                    size_t off = (((size_t)(b*NH + h))*SEQ + t)*DK + d;
                    if (part == 0)      g_Qh[off] = __float2half_rn(v * 0.1803368801f); // 0.125*log2(e)
                    else if (part == 1) g_Kh[off] = __float2half_rn(v);
                    else                g_Vh[off] = __float2half_rn(v);
                } else {
                    Cout[(size_t)gm*DM + gn] = v;
                }
            }
            __syncwarp();
        }
    }
}

// ============================================================
// FlashAttention-2, all-fp16, 6-stage KV pipeline, one barrier
// per 2 key-tiles. Softmax uses ex2.approx.f16x2 (P computed
// directly in fp16 — half the MUFU issues) and the row-sum l is
// produced by an extra n=8 mma against a ones-fragment (no FADD
// chain, no shuffles). O += P V via ldmatrix.trans.
// ============================================================
#define KV_LD 72                       // halves per K/V row
#define KVBUF (64*KV_LD)               // halves per stage
#define ASTAGES 6
#define ATTN_SMEM (2*ASTAGES*KVBUF*2)  // 6 x K + 6 x V = 110592 B
#define ONES_H2 0x3C003C00u

__global__ __launch_bounds__(256, 2)
void attn_kernel()
{
    extern __shared__ char smraw[];
    __half* Ksm = (__half*)smraw;                 // 6 x 64 x 72
    __half* Vsm = Ksm + ASTAGES*KVBUF;            // 6 x 64 x 72

    const int tid  = threadIdx.x;
    const int warp = tid >> 5;
    const int lane = tid & 31;
    const int r    = lane >> 2;      // 0..7
    const int c    = lane & 3;       // 0..3
    const int q0   = blockIdx.x * 128;
    const int h    = blockIdx.y;
    const int b    = blockIdx.z;
    const size_t headbase = ((size_t)(b*NH + h))*SEQ*DK;

    // ---- Q fragments (fp16, pre-scaled incl. log2e) from gmem ----
    unsigned qf[4][4];
    {
        const __half* q_r0 = g_Qh + headbase + (size_t)(q0 + warp*16 + r)*DK;
        const __half* q_r1 = q_r0 + 8*DK;
        #pragma unroll
        for (int s = 0; s < 4; s++) {
            qf[s][0] = *(const unsigned*)(q_r0 + 16*s + 2*c);
            qf[s][1] = *(const unsigned*)(q_r1 + 16*s + 2*c);
            qf[s][2] = *(const unsigned*)(q_r0 + 16*s + 2*c + 8);
            qf[s][3] = *(const unsigned*)(q_r1 + 16*s + 2*c + 8);
        }
    }

    float Oacc[8][4];
    #pragma unroll
    for (int j=0;j<8;j++)
        #pragma unroll
        for (int e=0;e<4;e++) Oacc[j][e] = 0.0f;
    float mrow[2] = {-CUDART_INF_F, -CUDART_INF_F};
    float lrow[2] = {0.0f, 0.0f};

    const uint32_t kbase0 = smem_u32(Ksm);
    const uint32_t vbase0 = smem_u32(Vsm);

    auto preload = [&](int kt) {
        const int st = kt % ASTAGES;
        const size_t kb = headbase + (size_t)kt*64*DK;
        const uint32_t kd = kbase0 + (uint32_t)(st*KVBUF*2);
        const uint32_t vd = vbase0 + (uint32_t)(st*KVBUF*2);
        #pragma unroll
        for (int it = 0; it < 2; it++) {             // K: 512 x 16B
            int idx = tid + it*256;
            int row = idx >> 3, seg = idx & 7;
            cp_async16(kd + row*KV_LD*2 + seg*16, g_Kh + kb + (size_t)row*DK + seg*8);
        }
        #pragma unroll
        for (int it = 0; it < 2; it++) {             // V: 512 x 16B
            int idx = tid + it*256;
            int row = idx >> 3, seg = idx & 7;
            cp_async16(vd + row*KV_LD*2 + seg*16, g_Vh + kb + (size_t)row*DK + seg*8);
        }
    };

    preload(0); cp_commit();
    preload(1); cp_commit();
    preload(2); cp_commit();
    preload(3); cp_commit();

    const int n_off = ((lane >> 4) << 3) + (lane & 7);   // (group>>1)*8 + row
    const int c_off = ((lane >> 3) & 1) << 3;            // (group&1)*8
    const int t  = lane >> 3;
    const int rr = lane & 7;

    // one key-tile: S-mma, prefetch kt+4, softmax(f16x2 ex2), PV
    auto do_tile = [&](int kt) {
        const int st = kt % ASTAGES;
        const uint32_t kb32 = kbase0 + (uint32_t)(st*KVBUF*2);
        const uint32_t vb   = vbase0 + (uint32_t)(st*KVBUF*2);

        // ---- S = Q K^T ----
        float Sacc[8][4];
        #pragma unroll
        for (int j=0;j<8;j++)
            #pragma unroll
            for (int e=0;e<4;e++) Sacc[j][e] = 0.0f;
        #pragma unroll
        for (int s = 0; s < 4; s++) {
            #pragma unroll
            for (int jp = 0; jp < 4; jp++) {
                uint32_t addr = kb32 + (uint32_t)((((16*jp + n_off)*KV_LD) + 16*s + c_off)*2);
                unsigned b0,b1,b2,b3;
                ldsm_x4(b0, b1, b2, b3, addr);
                mma_f16(Sacc[2*jp  ], qf[s], b0, b1);
                mma_f16(Sacc[2*jp+1], qf[s], b2, b3);
            }
        }

        // prefetch tile kt+4 (stage (kt-2)%6 — last read before this
        // pair's barrier; disjoint from the pair's tiles)
        if (kt + 4 < SEQ/64) { preload(kt+4); cp_commit(); }

        // ---- online softmax (base-2, fp16 ex2) ----
        float mx0 = Sacc[0][0], mx1 = Sacc[0][2];
        #pragma unroll
        for (int j=0;j<8;j++) {
            mx0 = fmaxf(mx0, fmaxf(Sacc[j][0], Sacc[j][1]));
            mx1 = fmaxf(mx1, fmaxf(Sacc[j][2], Sacc[j][3]));
        }
        mx0 = fmaxf(mx0, __shfl_xor_sync(0xffffffffu, mx0, 1));
        mx0 = fmaxf(mx0, __shfl_xor_sync(0xffffffffu, mx0, 2));
        mx1 = fmaxf(mx1, __shfl_xor_sync(0xffffffffu, mx1, 1));
        mx1 = fmaxf(mx1, __shfl_xor_sync(0xffffffffu, mx1, 2));
        float mn0 = fmaxf(mrow[0], mx0), mn1 = fmaxf(mrow[1], mx1);
        float al0 = exp2f(mrow[0] - mn0), al1 = exp2f(mrow[1] - mn1);
        mrow[0] = mn0; mrow[1] = mn1;

        unsigned ph[16];
        #pragma unroll
        for (int j = 0; j < 8; j++) {
            ph[2*j  ] = ex2_h2(h2_as_u32(__floats2half2_rn(Sacc[j][0]-mn0, Sacc[j][1]-mn0)));
            ph[2*j+1] = ex2_h2(h2_as_u32(__floats2half2_rn(Sacc[j][2]-mn1, Sacc[j][3]-mn1)));
        }

        // row sums via mma against ones (n=8 tile; every output col = row sum)
        float Lacc[4] = {0.0f, 0.0f, 0.0f, 0.0f};
        #pragma unroll
        for (int s = 0; s < 4; s++)
            mma_f16(Lacc, &ph[4*s], ONES_H2, ONES_H2);
        lrow[0] = lrow[0]*al0 + Lacc[0];
        lrow[1] = lrow[1]*al1 + Lacc[2];

        #pragma unroll
        for (int j=0;j<8;j++) {
            Oacc[j][0] *= al0; Oacc[j][1] *= al0;
            Oacc[j][2] *= al1; Oacc[j][3] *= al1;
        }

        // ---- O += P V ----
        #pragma unroll
        for (int s = 0; s < 4; s++) {
            const unsigned* af = &ph[4*s];
            #pragma unroll
            for (int g = 0; g < 4; g++) {
                uint32_t addr = vb + (uint32_t)(((16*s + (t&1)*8 + rr)*KV_LD + (t>>1)*8 + g*16)*2);
                unsigned r0,r1,r2,r3;
                asm volatile(
                    "ldmatrix.sync.aligned.m8n8.x4.trans.shared.b16 {%0,%1,%2,%3}, [%4];\n"
                    : "=r"(r0),"=r"(r1),"=r"(r2),"=r"(r3) : "r"(addr));
                mma_f16(Oacc[2*g  ], af, r0, r1);
                mma_f16(Oacc[2*g+1], af, r2, r3);
            }
        }
    };

    #pragma unroll 1
    for (int kt = 0; kt < SEQ/64; kt += 2) {
        if (kt < SEQ/64 - 2) cp_wait<2>(); else cp_wait<0>();
        __syncthreads();
        do_tile(kt);
        do_tile(kt + 1);
    }

    // ---- normalize + write ctx fp16 [B,T,DM] ----
    {
        float inv0 = 1.0f / lrow[0];
        float inv1 = 1.0f / lrow[1];
        __half* row0 = g_ctxh + ((size_t)(b*SEQ + q0 + warp*16 + r    ))*DM + h*DK;
        __half* row1 = g_ctxh + ((size_t)(b*SEQ + q0 + warp*16 + r + 8))*DM + h*DK;
        #pragma unroll
        for (int j = 0; j < 8; j++) {
            *(__half2*)(row0 + 8*j + 2*c) = __floats2half2_rn(Oacc[j][0]*inv0, Oacc[j][1]*inv0);
            *(__half2*)(row1 + 8*j + 2*c) = __floats2half2_rn(Oacc[j][2]*inv1, Oacc[j][3]*inv1);
        }
    }
}

// ============================================================
extern "C" void kernel_launch(void* const* d_in, const int* in_sizes, int n_in,
                              void* d_out, int out_size)
{
    (void)in_sizes; (void)n_in; (void)out_size;
    const float* x     = (const float*)d_in[0];
    const float* w_qkv = (const float*)d_in[1];
    const float* b_qkv = (const float*)d_in[2];
    const float* w_out = (const float*)d_in[3];
    const float* b_out = (const float*)d_in[4];
    float* out = (float*)d_out;

    cudaFuncSetAttribute(gemm_f16_kernel<0>, cudaFuncAttributeMaxDynamicSharedMemorySize, GEMM_SMEM);
    cudaFuncSetAttribute(gemm_f16_kernel<1>, cudaFuncAttributeMaxDynamicSharedMemorySize, GEMM_SMEM);
    cudaFuncSetAttribute(attn_kernel, cudaFuncAttributeMaxDynamicSharedMemorySize, ATTN_SMEM);

    void *xh, *wqkvh, *wouth;
    cudaGetSymbolAddress(&xh,    g_xh);
    cudaGetSymbolAddress(&wqkvh, g_wqkvh);
    cudaGetSymbolAddress(&wouth, g_wouth);

    // 0) fused fp32 -> fp16 prepass (one launch)
    prep_kernel<<<1024, 256>>>((const float4*)x, (const float4*)w_qkv, (const float4*)w_out,
                               (uint2*)xh, (uint2*)wqkvh, (uint2*)wouth);

    // 1) QKV projection -> Q/K/V fp16 scratch
    gemm_f16_kernel<0><<<dim3(3*DM/128, M_TOT/128), 256, GEMM_SMEM>>>(b_qkv, nullptr);
    // 2) attention -> ctx fp16 scratch
    attn_kernel<<<dim3(SEQ/128, NH, BATCH), 256, ATTN_SMEM>>>();
    // 3) output projection -> d_out fp32
    gemm_f16_kernel<1><<<dim3(DM/128, M_TOT/128), 256, GEMM_SMEM>>>(b_out, out);
}

// round 15
// speedup vs baseline: 1.0917x; 1.0102x over previous
#include <cuda_runtime.h>
#include <cuda_fp16.h>
#include <math_constants.h>
#include <cstdint>

#define BATCH 2
#define SEQ   2048
#define DM    1024
#define NH    16
#define DK    64
#define M_TOT (BATCH*SEQ)   // 4096

// -------- scratch (device globals: allocation-free) --------
__device__ __half g_Qh [(size_t)BATCH*NH*SEQ*DK];   // pre-scaled by 0.125*log2(e)
__device__ __half g_Kh [(size_t)BATCH*NH*SEQ*DK];
__device__ __half g_Vh [(size_t)BATCH*NH*SEQ*DK];
__device__ __half g_ctxh[(size_t)M_TOT*DM];
__device__ __half g_xh   [(size_t)M_TOT*DM];
__device__ __half g_wqkvh[(size_t)3*DM*DM];
__device__ __half g_wouth[(size_t)DM*DM];

// -------- helpers --------
__device__ __forceinline__ void cp_async16(uint32_t smem, const void* gmem) {
    asm volatile("cp.async.cg.shared.global [%0], [%1], 16;\n" :: "r"(smem), "l"(gmem));
}
__device__ __forceinline__ void cp_commit() { asm volatile("cp.async.commit_group;\n"); }
template<int N> __device__ __forceinline__ void cp_wait() {
    asm volatile("cp.async.wait_group %0;\n" :: "n"(N));
}
__device__ __forceinline__ unsigned h2_as_u32(__half2 h) {
    return *reinterpret_cast<unsigned*>(&h);
}
__device__ __forceinline__ uint32_t smem_u32(const void* p) {
    return (uint32_t)__cvta_generic_to_shared(p);
}
__device__ __forceinline__ void ldsm_x4(unsigned& r0, unsigned& r1, unsigned& r2, unsigned& r3,
                                        uint32_t addr) {
    asm volatile("ldmatrix.sync.aligned.m8n8.x4.shared.b16 {%0,%1,%2,%3}, [%4];"
                 : "=r"(r0), "=r"(r1), "=r"(r2), "=r"(r3) : "r"(addr));
}
__device__ __forceinline__ void mma_f16(float* d, const unsigned* a, unsigned b0, unsigned b1) {
    asm volatile(
        "mma.sync.aligned.m16n8k16.row.col.f32.f16.f16.f32 "
        "{%0,%1,%2,%3},{%4,%5,%6,%7},{%8,%9},{%0,%1,%2,%3};\n"
        : "+f"(d[0]),"+f"(d[1]),"+f"(d[2]),"+f"(d[3])
        : "r"(a[0]),"r"(a[1]),"r"(a[2]),"r"(a[3]),"r"(b0),"r"(b1));
}
__device__ __forceinline__ unsigned ex2_h2(unsigned x) {
    unsigned d;
    asm("ex2.approx.f16x2 %0, %1;" : "=r"(d) : "r"(x));
    return d;
}

// ============================================================
// fused fp32 -> fp16 conversion prepass (one launch)
// ============================================================
__global__ void prep_kernel(const float4* __restrict__ x,
                            const float4* __restrict__ wq,
                            const float4* __restrict__ wo,
                            uint2* __restrict__ xh,
                            uint2* __restrict__ wqh,
                            uint2* __restrict__ woh)
{
    const int stride = gridDim.x * blockDim.x;
    const int t0 = blockIdx.x*blockDim.x + threadIdx.x;
    #pragma unroll 1
    for (int i = t0; i < (M_TOT*DM)/4; i += stride) {
        float4 v = x[i];
        xh[i] = make_uint2(h2_as_u32(__floats2half2_rn(v.x, v.y)),
                           h2_as_u32(__floats2half2_rn(v.z, v.w)));
    }
    #pragma unroll 1
    for (int i = t0; i < (3*DM*DM)/4; i += stride) {
        float4 v = wq[i];
        wqh[i] = make_uint2(h2_as_u32(__floats2half2_rn(v.x, v.y)),
                            h2_as_u32(__floats2half2_rn(v.z, v.w)));
    }
    #pragma unroll 1
    for (int i = t0; i < (DM*DM)/4; i += stride) {
        float4 v = wo[i];
        woh[i] = make_uint2(h2_as_u32(__floats2half2_rn(v.x, v.y)),
                            h2_as_u32(__floats2half2_rn(v.z, v.w)));
    }
}

// ============================================================
// fp16 mma GEMM (round-10 best schedule):  C = A * W^T + bias
// CTA 128x128, BK=64, 8 warps, warp tile 32x64. 3-stage cp.async
// pipeline, one __syncthreads per iteration; single prefetch
// burst issued after the first k-step.
// MODE 0 -> Q(x0.125*log2e)/K/V fp16 scratch; MODE 1 -> fp32 out.
// ============================================================
#define GSTG 16384
#define GEMM_SMEM (6*GSTG)   // 3 x A(16KB) + 3 x B(16KB)

template<int MODE>
__global__ __launch_bounds__(256, 2)
void gemm_f16_kernel(const float* __restrict__ bias, float* __restrict__ Cout)
{
    extern __shared__ char smraw[];
    const uint32_t sa = smem_u32(smraw);            // A stages [0,3)
    const uint32_t sb = sa + 3*GSTG;                // B stages [0,3)

    const int tid  = threadIdx.x;
    const int warp = tid >> 5;
    const int lane = tid & 31;
    const int wm   = warp >> 1;      // 0..3
    const int wn   = warp & 1;       // 0..1
    const int bm   = blockIdx.y;
    const int bn   = blockIdx.x;

    const __half* Ab = (MODE == 0 ? g_xh : g_ctxh) + (size_t)(bm*128)*1024;
    const __half* Wb = (MODE == 0 ? g_wqkvh : g_wouth) + (size_t)(bn*128)*1024;

    float acc[2][8][4];
    #pragma unroll
    for (int x=0;x<2;x++)
        #pragma unroll
        for (int j=0;j<8;j++)
            #pragma unroll
            for (int e=0;e<4;e++) acc[x][j][e] = 0.0f;

    auto preload = [&](int ci) {
        const int st = ci % 3;
        const uint32_t ab = sa + st*GSTG;
        const uint32_t bb = sb + st*GSTG;
        #pragma unroll
        for (int it = 0; it < 8; it++) {
            int s = tid + it*256;                   // 0..2047
            if (s < 1024) {                          // A: 128 rows x 8 segs(16B)
                int row = s >> 3, seg = s & 7;
                cp_async16(ab + row*128 + ((seg*16) ^ ((row&7)*16)),
                           Ab + (size_t)row*1024 + ci*64 + seg*8);
            } else {                                 // B
                int q = s - 1024;
                int row = q >> 3, seg = q & 7;
                cp_async16(bb + row*128 + ((seg*16) ^ ((row&7)*16)),
                           Wb + (size_t)row*1024 + ci*64 + seg*8);
            }
        }
    };

    preload(0); cp_commit();
    preload(1); cp_commit();

    for (int i = 0; i < 16; i++) {
        if (i < 15) cp_wait<1>(); else cp_wait<0>();
        __syncthreads();

        const uint32_t ab = sa + (i%3)*GSTG;
        const uint32_t bb = sb + (i%3)*GSTG;

        auto ks_step = [&](int ks) {
            unsigned af[2][4];
            #pragma unroll
            for (int x = 0; x < 2; x++) {
                int lrow = wm*32 + x*16 + (lane & 15);
                int kb   = ks*32 + (lane >> 4)*16;
                ldsm_x4(af[x][0], af[x][1], af[x][2], af[x][3],
                        ab + lrow*128 + (kb ^ ((lrow&7)*16)));
            }
            #pragma unroll
            for (int jj = 0; jj < 4; jj++) {
                int nrow = wn*64 + jj*16 + (lane & 7) + (lane >> 4)*8;
                int kb   = ks*32 + ((lane >> 3) & 1)*16;
                unsigned b0,b1,b2,b3;
                ldsm_x4(b0, b1, b2, b3, bb + nrow*128 + (kb ^ ((nrow&7)*16)));
                #pragma unroll
                for (int x = 0; x < 2; x++) {
                    mma_f16(acc[x][2*jj  ], af[x], b0, b1);
                    mma_f16(acc[x][2*jj+1], af[x], b2, b3);
                }
            }
        };

        // first k-step right after the barrier -> tensor pipe restarts at once
        ks_step(0);
        if (i + 2 < 16) { preload(i+2); cp_commit(); }
        #pragma unroll
        for (int ks = 1; ks < 4; ks++) ks_step(ks);
    }
    __syncthreads();   // all fragment reads done before stage overlays smem

    // ---- epilogue via per-warp smem staging ----
    float* stage = (float*)smraw + warp*16*20;
    const int r = lane >> 2, c = lane & 3;
    #pragma unroll
    for (int x = 0; x < 2; x++) {
        #pragma unroll
        for (int jj = 0; jj < 4; jj++) {
            stage[ r    *20 + 2*c    ] = acc[x][2*jj][0];
            stage[ r    *20 + 2*c + 1] = acc[x][2*jj][1];
            stage[(r+8) *20 + 2*c    ] = acc[x][2*jj][2];
            stage[(r+8) *20 + 2*c + 1] = acc[x][2*jj][3];
            stage[ r    *20 + 8 + 2*c    ] = acc[x][2*jj+1][0];
            stage[ r    *20 + 8 + 2*c + 1] = acc[x][2*jj+1][1];
            stage[(r+8) *20 + 8 + 2*c    ] = acc[x][2*jj+1][2];
            stage[(r+8) *20 + 8 + 2*c + 1] = acc[x][2*jj+1][3];
            __syncwarp();
            #pragma unroll
            for (int e = 0; e < 8; e++) {
                int idx = e*32 + lane;
                int rr = idx >> 4, cc = idx & 15;
                int gm = bm*128 + wm*32 + x*16 + rr;
                int gn = bn*128 + wn*64 + jj*16 + cc;
                float v = stage[rr*20 + cc] + __ldg(&bias[gn]);
                if (MODE == 0) {
                    int b = gm >> 11, t = gm & 2047;
                    int part = gn >> 10, rem = gn & 1023;
                    int h = rem >> 6, d = rem & 63;
                    size_t off = (((size_t)(b*NH + h))*SEQ + t)*DK + d;
                    if (part == 0)      g_Qh[off] = __float2half_rn(v * 0.1803368801f); // 0.125*log2(e)
                    else if (part == 1) g_Kh[off] = __float2half_rn(v);
                    else                g_Vh[off] = __float2half_rn(v);
                } else {
                    Cout[(size_t)gm*DM + gn] = v;
                }
            }
            __syncwarp();
        }
    }
}

// ============================================================
// FlashAttention-2, all-fp16, 4 warps x 32 q-rows (128 thr/CTA,
// still 128 q/CTA). K/V ldmatrix fragments amortized over 2x
// rows; V-ldsm shared across both m16 subtiles. 6-stage KV
// pipeline, one barrier per 2 key-tiles; softmax via
// ex2.approx.f16x2; row-sum l via mma against ones.
// ============================================================
#define KV_LD 72                       // halves per K/V row
#define KVBUF (64*KV_LD)               // halves per stage
#define ASTAGES 6
#define ATTN_SMEM (2*ASTAGES*KVBUF*2)  // 6 x K + 6 x V = 110592 B
#define ONES_H2 0x3C003C00u

__global__ __launch_bounds__(128, 2)
void attn_kernel()
{
    extern __shared__ char smraw[];
    __half* Ksm = (__half*)smraw;                 // 6 x 64 x 72
    __half* Vsm = Ksm + ASTAGES*KVBUF;            // 6 x 64 x 72

    const int tid  = threadIdx.x;
    const int warp = tid >> 5;       // 0..3
    const int lane = tid & 31;
    const int r    = lane >> 2;      // 0..7
    const int c    = lane & 3;       // 0..3
    const int q0   = blockIdx.x * 128;
    const int h    = blockIdx.y;
    const int b    = blockIdx.z;
    const size_t headbase = ((size_t)(b*NH + h))*SEQ*DK;

    // ---- Q fragments: warp owns rows [32*warp, 32*warp+32) ----
    // qf[s][x][i]: A-fragment for m16-subtile x at k-step s
    unsigned qf[4][2][4];
    {
        #pragma unroll
        for (int x = 0; x < 2; x++) {
            const __half* q_r0 = g_Qh + headbase + (size_t)(q0 + warp*32 + x*16 + r)*DK;
            const __half* q_r1 = q_r0 + 8*DK;
            #pragma unroll
            for (int s = 0; s < 4; s++) {
                qf[s][x][0] = *(const unsigned*)(q_r0 + 16*s + 2*c);
                qf[s][x][1] = *(const unsigned*)(q_r1 + 16*s + 2*c);
                qf[s][x][2] = *(const unsigned*)(q_r0 + 16*s + 2*c + 8);
                qf[s][x][3] = *(const unsigned*)(q_r1 + 16*s + 2*c + 8);
            }
        }
    }

    float Oacc[2][8][4];
    #pragma unroll
    for (int x=0;x<2;x++)
        #pragma unroll
        for (int j=0;j<8;j++)
            #pragma unroll
            for (int e=0;e<4;e++) Oacc[x][j][e] = 0.0f;
    float mrow[2][2] = {{-CUDART_INF_F,-CUDART_INF_F},{-CUDART_INF_F,-CUDART_INF_F}};
    float lrow[2][2] = {{0.0f,0.0f},{0.0f,0.0f}};

    const uint32_t kbase0 = smem_u32(Ksm);
    const uint32_t vbase0 = smem_u32(Vsm);

    auto preload = [&](int kt) {
        const int st = kt % ASTAGES;
        const size_t kb = headbase + (size_t)kt*64*DK;
        const uint32_t kd = kbase0 + (uint32_t)(st*KVBUF*2);
        const uint32_t vd = vbase0 + (uint32_t)(st*KVBUF*2);
        #pragma unroll
        for (int it = 0; it < 4; it++) {             // K: 512 x 16B over 128 thr
            int idx = tid + it*128;
            int row = idx >> 3, seg = idx & 7;
            cp_async16(kd + row*KV_LD*2 + seg*16, g_Kh + kb + (size_t)row*DK + seg*8);
        }
        #pragma unroll
        for (int it = 0; it < 4; it++) {             // V: 512 x 16B
            int idx = tid + it*128;
            int row = idx >> 3, seg = idx & 7;
            cp_async16(vd + row*KV_LD*2 + seg*16, g_Vh + kb + (size_t)row*DK + seg*8);
        }
    };

    preload(0); cp_commit();
    preload(1); cp_commit();
    preload(2); cp_commit();
    preload(3); cp_commit();

    const int n_off = ((lane >> 4) << 3) + (lane & 7);   // (group>>1)*8 + row
    const int c_off = ((lane >> 3) & 1) << 3;            // (group&1)*8
    const int t  = lane >> 3;
    const int rr = lane & 7;

    // one key-tile: S-mma, prefetch kt+4, softmax(f16x2 ex2), PV
    auto do_tile = [&](int kt) {
        const int st = kt % ASTAGES;
        const uint32_t kb32 = kbase0 + (uint32_t)(st*KVBUF*2);
        const uint32_t vb   = vbase0 + (uint32_t)(st*KVBUF*2);

        // ---- S = Q K^T : one K-ldsm feeds both m16 subtiles ----
        float Sacc[2][8][4];
        #pragma unroll
        for (int x=0;x<2;x++)
            #pragma unroll
            for (int j=0;j<8;j++)
                #pragma unroll
                for (int e=0;e<4;e++) Sacc[x][j][e] = 0.0f;
        #pragma unroll
        for (int s = 0; s < 4; s++) {
            #pragma unroll
            for (int jp = 0; jp < 4; jp++) {
                uint32_t addr = kb32 + (uint32_t)((((16*jp + n_off)*KV_LD) + 16*s + c_off)*2);
                unsigned b0,b1,b2,b3;
                ldsm_x4(b0, b1, b2, b3, addr);
                #pragma unroll
                for (int x = 0; x < 2; x++) {
                    mma_f16(Sacc[x][2*jp  ], qf[s][x], b0, b1);
                    mma_f16(Sacc[x][2*jp+1], qf[s][x], b2, b3);
                }
            }
        }

        // prefetch tile kt+4 (stage (kt-2)%6 — dead since before the barrier)
        if (kt + 4 < SEQ/64) { preload(kt+4); cp_commit(); }

        // ---- online softmax (base-2, fp16 ex2), per subtile ----
        unsigned ph[2][16];
        float al[2][2];
        #pragma unroll
        for (int x = 0; x < 2; x++) {
            float mx0 = Sacc[x][0][0], mx1 = Sacc[x][0][2];
            #pragma unroll
            for (int j=0;j<8;j++) {
                mx0 = fmaxf(mx0, fmaxf(Sacc[x][j][0], Sacc[x][j][1]));
                mx1 = fmaxf(mx1, fmaxf(Sacc[x][j][2], Sacc[x][j][3]));
            }
            mx0 = fmaxf(mx0, __shfl_xor_sync(0xffffffffu, mx0, 1));
            mx0 = fmaxf(mx0, __shfl_xor_sync(0xffffffffu, mx0, 2));
            mx1 = fmaxf(mx1, __shfl_xor_sync(0xffffffffu, mx1, 1));
            mx1 = fmaxf(mx1, __shfl_xor_sync(0xffffffffu, mx1, 2));
            float mn0 = fmaxf(mrow[x][0], mx0), mn1 = fmaxf(mrow[x][1], mx1);
            al[x][0] = exp2f(mrow[x][0] - mn0);
            al[x][1] = exp2f(mrow[x][1] - mn1);
            mrow[x][0] = mn0; mrow[x][1] = mn1;

            #pragma unroll
            for (int j = 0; j < 8; j++) {
                ph[x][2*j  ] = ex2_h2(h2_as_u32(__floats2half2_rn(Sacc[x][j][0]-mn0, Sacc[x][j][1]-mn0)));
                ph[x][2*j+1] = ex2_h2(h2_as_u32(__floats2half2_rn(Sacc[x][j][2]-mn1, Sacc[x][j][3]-mn1)));
            }

            // row sums via mma against ones
            float Lacc[4] = {0.0f, 0.0f, 0.0f, 0.0f};
            #pragma unroll
            for (int s = 0; s < 4; s++)
                mma_f16(Lacc, &ph[x][4*s], ONES_H2, ONES_H2);
            lrow[x][0] = lrow[x][0]*al[x][0] + Lacc[0];
            lrow[x][1] = lrow[x][1]*al[x][1] + Lacc[2];

            #pragma unroll
            for (int j=0;j<8;j++) {
                Oacc[x][j][0] *= al[x][0]; Oacc[x][j][1] *= al[x][0];
                Oacc[x][j][2] *= al[x][1]; Oacc[x][j][3] *= al[x][1];
            }
        }

        // ---- O += P V : one V-ldsm feeds both subtiles ----
        #pragma unroll
        for (int s = 0; s < 4; s++) {
            #pragma unroll
            for (int g = 0; g < 4; g++) {
                uint32_t addr = vb + (uint32_t)(((16*s + (t&1)*8 + rr)*KV_LD + (t>>1)*8 + g*16)*2);
                unsigned r0,r1,r2,r3;
                asm volatile(
                    "ldmatrix.sync.aligned.m8n8.x4.trans.shared.b16 {%0,%1,%2,%3}, [%4];\n"
                    : "=r"(r0),"=r"(r1),"=r"(r2),"=r"(r3) : "r"(addr));
                #pragma unroll
                for (int x = 0; x < 2; x++) {
                    mma_f16(Oacc[x][2*g  ], &ph[x][4*s], r0, r1);
                    mma_f16(Oacc[x][2*g+1], &ph[x][4*s], r2, r3);
                }
            }
        }
    };

    #pragma unroll 1
    for (int kt = 0; kt < SEQ/64; kt += 2) {
        if (kt < SEQ/64 - 2) cp_wait<2>(); else cp_wait<0>();
        __syncthreads();
        do_tile(kt);
        do_tile(kt + 1);
    }

    // ---- normalize + write ctx fp16 [B,T,DM] ----
    #pragma unroll
    for (int x = 0; x < 2; x++) {
        float inv0 = 1.0f / lrow[x][0];
        float inv1 = 1.0f / lrow[x][1];
        __half* row0 = g_ctxh + ((size_t)(b*SEQ + q0 + warp*32 + x*16 + r    ))*DM + h*DK;
        __half* row1 = g_ctxh + ((size_t)(b*SEQ + q0 + warp*32 + x*16 + r + 8))*DM + h*DK;
        #pragma unroll
        for (int j = 0; j < 8; j++) {
            *(__half2*)(row0 + 8*j + 2*c) = __floats2half2_rn(Oacc[x][j][0]*inv0, Oacc[x][j][1]*inv0);
            *(__half2*)(row1 + 8*j + 2*c) = __floats2half2_rn(Oacc[x][j][2]*inv1, Oacc[x][j][3]*inv1);
        }
    }
}

// ============================================================
extern "C" void kernel_launch(void* const* d_in, const int* in_sizes, int n_in,
                              void* d_out, int out_size)
{
    (void)in_sizes; (void)n_in; (void)out_size;
    const float* x     = (const float*)d_in[0];
    const float* w_qkv = (const float*)d_in[1];
    const float* b_qkv = (const float*)d_in[2];
    const float* w_out = (const float*)d_in[3];
    const float* b_out = (const float*)d_in[4];
    float* out = (float*)d_out;

    cudaFuncSetAttribute(gemm_f16_kernel<0>, cudaFuncAttributeMaxDynamicSharedMemorySize, GEMM_SMEM);
    cudaFuncSetAttribute(gemm_f16_kernel<1>, cudaFuncAttributeMaxDynamicSharedMemorySize, GEMM_SMEM);
    cudaFuncSetAttribute(attn_kernel, cudaFuncAttributeMaxDynamicSharedMemorySize, ATTN_SMEM);

    void *xh, *wqkvh, *wouth;
    cudaGetSymbolAddress(&xh,    g_xh);
    cudaGetSymbolAddress(&wqkvh, g_wqkvh);
    cudaGetSymbolAddress(&wouth, g_wouth);

    // 0) fused fp32 -> fp16 prepass (one launch)
    prep_kernel<<<1024, 256>>>((const float4*)x, (const float4*)w_qkv, (const float4*)w_out,
                               (uint2*)xh, (uint2*)wqkvh, (uint2*)wouth);

    // 1) QKV projection -> Q/K/V fp16 scratch
    gemm_f16_kernel<0><<<dim3(3*DM/128, M_TOT/128), 256, GEMM_SMEM>>>(b_qkv, nullptr);
    // 2) attention -> ctx fp16 scratch
    attn_kernel<<<dim3(SEQ/128, NH, BATCH), 128, ATTN_SMEM>>>();
    // 3) output projection -> d_out fp32
    gemm_f16_kernel<1><<<dim3(DM/128, M_TOT/128), 256, GEMM_SMEM>>>(b_out, out);
}